// round 4
// baseline (speedup 1.0000x reference)
#include <cuda_runtime.h>
#include <math.h>

#define NN 100000
#define EE 1600000
#define FIN 64
#define HH 32
#define NCH 196          // ceil(NN/512)

// ---------------- device scratch (static, allocation-free) ----------------
__device__ __align__(16) float g_xr[NN * HH];     // rel-transformed features for gather
__device__ __align__(16) float g_rt[NN * HH];     // root-transformed features (+bias)
__device__ __align__(16) float g_agg[NN * HH];    // gathered aggregation
__device__ __align__(16) float g_pvsrc[NN * 2];   // per-node (h2 . Wp_rel, h2 . Wv_rel)
__device__ __align__(16) float g_pvrt[NN * 2];    // per-node (h2 . Wp_root + bp, h2 . Wv_root + bv)
__device__ __align__(16) float g_mask[NN];
__device__ __align__(16) float g_pm[NN];
__device__ __align__(16) int2  g_edges[EE];       // dst-sorted (src, w-bits)
__device__ int g_cnt[NN];
__device__ int g_off[NN];
__device__ int g_wpos[NN];
__device__ int g_bsum[NCH];
__device__ int g_bbase[NCH];
__device__ unsigned g_maxkey;
__device__ float g_sum;

// ---------------- fused: xr = x@Win_rel, rt = x@Win_root + bin, zero cnt/scalars ----------------
__global__ void k_xw64f(const float* __restrict__ x, const float* __restrict__ Wrel,
                        const float* __restrict__ Wroot, const float* __restrict__ b) {
    __shared__ float sWa[FIN * HH];
    __shared__ float sWb[FIN * HH];
    __shared__ float sb[HH];
    for (int i = threadIdx.x; i < FIN * HH; i += blockDim.x) {
        sWa[i] = Wrel[i];
        sWb[i] = Wroot[i];
    }
    if (threadIdx.x < HH) sb[threadIdx.x] = b[threadIdx.x];
    __syncthreads();
    int node = blockIdx.x * blockDim.x + threadIdx.x;
    if (node == 0) { g_maxkey = 0u; g_sum = 0.f; }
    if (node >= NN) return;
    g_cnt[node] = 0;
    float ar[HH], br[HH];
#pragma unroll
    for (int j = 0; j < HH; j++) { ar[j] = 0.f; br[j] = sb[j]; }
    const float4* xv = (const float4*)(x + (size_t)node * FIN);
#pragma unroll
    for (int k4 = 0; k4 < FIN / 4; k4++) {
        float4 xk = xv[k4];
        float xs[4] = {xk.x, xk.y, xk.z, xk.w};
#pragma unroll
        for (int kk = 0; kk < 4; kk++) {
            const float4* wa = (const float4*)(sWa + (k4 * 4 + kk) * HH);
            const float4* wb = (const float4*)(sWb + (k4 * 4 + kk) * HH);
#pragma unroll
            for (int j4 = 0; j4 < HH / 4; j4++) {
                float4 a = wa[j4];
                float4 bb = wb[j4];
                ar[j4 * 4 + 0] += xs[kk] * a.x;  br[j4 * 4 + 0] += xs[kk] * bb.x;
                ar[j4 * 4 + 1] += xs[kk] * a.y;  br[j4 * 4 + 1] += xs[kk] * bb.y;
                ar[j4 * 4 + 2] += xs[kk] * a.z;  br[j4 * 4 + 2] += xs[kk] * bb.z;
                ar[j4 * 4 + 3] += xs[kk] * a.w;  br[j4 * 4 + 3] += xs[kk] * bb.w;
            }
        }
    }
    float4* oa = (float4*)(g_xr + (size_t)node * HH);
    float4* ob = (float4*)(g_rt + (size_t)node * HH);
#pragma unroll
    for (int j4 = 0; j4 < HH / 4; j4++) {
        oa[j4] = make_float4(ar[j4 * 4], ar[j4 * 4 + 1], ar[j4 * 4 + 2], ar[j4 * 4 + 3]);
        ob[j4] = make_float4(br[j4 * 4], br[j4 * 4 + 1], br[j4 * 4 + 2], br[j4 * 4 + 3]);
    }
}

// ---------------- CSR build: histogram, 3-phase scan, scatter ----------------
__global__ void k_hist(const int* __restrict__ ei) {
    int e = blockIdx.x * blockDim.x + threadIdx.x;
    if (e >= EE) return;
    atomicAdd(&g_cnt[__ldg(ei + EE + e)], 1);
}

__global__ void k_scan1() {   // 196 blocks x 512: block sums
    __shared__ int sh[512];
    int i = blockIdx.x * 512 + threadIdx.x;
    int v = (i < NN) ? g_cnt[i] : 0;
    sh[threadIdx.x] = v;
    __syncthreads();
#pragma unroll
    for (int s = 256; s; s >>= 1) {
        if (threadIdx.x < s) sh[threadIdx.x] += sh[threadIdx.x + s];
        __syncthreads();
    }
    if (threadIdx.x == 0) g_bsum[blockIdx.x] = sh[0];
}

__global__ void k_scan2() {   // 1 block x 256: exclusive scan of block sums
    __shared__ int sh[256];
    int tid = threadIdx.x;
    int v = (tid < NCH) ? g_bsum[tid] : 0;
    sh[tid] = v;
    __syncthreads();
    for (int off = 1; off < 256; off <<= 1) {
        int t = (tid >= off) ? sh[tid - off] : 0;
        __syncthreads();
        sh[tid] += t;
        __syncthreads();
    }
    if (tid < NCH) g_bbase[tid] = sh[tid] - v;
}

__global__ void k_scan3() {   // 196 blocks x 512: in-chunk exclusive scan + base
    __shared__ int sh[512];
    int tid = threadIdx.x;
    int i = blockIdx.x * 512 + tid;
    int v = (i < NN) ? g_cnt[i] : 0;
    sh[tid] = v;
    __syncthreads();
    for (int off = 1; off < 512; off <<= 1) {
        int t = (tid >= off) ? sh[tid - off] : 0;
        __syncthreads();
        sh[tid] += t;
        __syncthreads();
    }
    if (i < NN) {
        int excl = sh[tid] - v + g_bbase[blockIdx.x];
        g_off[i] = excl;
        g_wpos[i] = excl;
    }
}

__global__ void k_scatter(const int* __restrict__ ei, const float* __restrict__ ew) {
    int e = blockIdx.x * blockDim.x + threadIdx.x;
    if (e >= EE) return;
    int s = __ldg(ei + e);
    int d = __ldg(ei + EE + e);
    float w = __ldg(ew + e);
    int pos = atomicAdd(&g_wpos[d], 1);
    g_edges[pos] = make_int2(s, __float_as_int(w));
}

// ---------------- gather: one warp per dst node, lane = feature column ----------------
__global__ void k_gather32(const int* __restrict__ curp, int do_mask) {
    int gw = (blockIdx.x * blockDim.x + threadIdx.x) >> 5;
    int lane = threadIdx.x & 31;
    if (gw >= NN) return;
    int beg = g_off[gw];
    int cnt = g_cnt[gw];
    int cur = do_mask ? __ldg(curp) : -1;
    float acc = 0.f;
    int hit = 0;
    for (int base = 0; base < cnt; base += 32) {
        int idx = base + lane;
        int2 rec = (idx < cnt) ? g_edges[beg + idx] : make_int2(0, 0);
        int m = min(32, cnt - base);
        for (int t = 0; t < m; t++) {
            int src = __shfl_sync(0xFFFFFFFFu, rec.x, t);
            float w = __int_as_float(__shfl_sync(0xFFFFFFFFu, rec.y, t));
            acc += w * g_xr[(size_t)src * HH + lane];
            hit |= (src == cur);
        }
    }
    g_agg[(size_t)gw * HH + lane] = acc;
    if (do_mask && lane == 0) g_mask[gw] = hit ? 1.0f : 0.0f;
}

// ---------------- h1 = relu(agg + rt); g_xr = h1@Wh_rel; g_rt = h1@Wh_root + bh ----------------
__global__ void k_node1(const float* __restrict__ Whrel, const float* __restrict__ Whroot,
                        const float* __restrict__ bh) {
    __shared__ float sWa[HH * HH];
    __shared__ float sWb[HH * HH];
    __shared__ float sb[HH];
    for (int i = threadIdx.x; i < HH * HH; i += blockDim.x) {
        sWa[i] = Whrel[i];
        sWb[i] = Whroot[i];
    }
    if (threadIdx.x < HH) sb[threadIdx.x] = bh[threadIdx.x];
    __syncthreads();
    int node = blockIdx.x * blockDim.x + threadIdx.x;
    if (node >= NN) return;
    float h1[HH];
    const float4* av = (const float4*)(g_agg + (size_t)node * HH);
    const float4* rv = (const float4*)(g_rt + (size_t)node * HH);
#pragma unroll
    for (int j4 = 0; j4 < HH / 4; j4++) {
        float4 a = av[j4];
        float4 r = rv[j4];
        h1[j4 * 4 + 0] = fmaxf(a.x + r.x, 0.f);
        h1[j4 * 4 + 1] = fmaxf(a.y + r.y, 0.f);
        h1[j4 * 4 + 2] = fmaxf(a.z + r.z, 0.f);
        h1[j4 * 4 + 3] = fmaxf(a.w + r.w, 0.f);
    }
    float acc[HH];
#pragma unroll
    for (int j = 0; j < HH; j++) acc[j] = 0.f;
#pragma unroll
    for (int k = 0; k < HH; k++) {
        float hk = h1[k];
        const float4* w4 = (const float4*)(sWa + k * HH);
#pragma unroll
        for (int j4 = 0; j4 < HH / 4; j4++) {
            float4 w = w4[j4];
            acc[j4 * 4 + 0] += hk * w.x;
            acc[j4 * 4 + 1] += hk * w.y;
            acc[j4 * 4 + 2] += hk * w.z;
            acc[j4 * 4 + 3] += hk * w.w;
        }
    }
    float4* oa = (float4*)(g_xr + (size_t)node * HH);
#pragma unroll
    for (int j4 = 0; j4 < HH / 4; j4++)
        oa[j4] = make_float4(acc[j4 * 4], acc[j4 * 4 + 1], acc[j4 * 4 + 2], acc[j4 * 4 + 3]);
#pragma unroll
    for (int j = 0; j < HH; j++) acc[j] = sb[j];
#pragma unroll
    for (int k = 0; k < HH; k++) {
        float hk = h1[k];
        const float4* w4 = (const float4*)(sWb + k * HH);
#pragma unroll
        for (int j4 = 0; j4 < HH / 4; j4++) {
            float4 w = w4[j4];
            acc[j4 * 4 + 0] += hk * w.x;
            acc[j4 * 4 + 1] += hk * w.y;
            acc[j4 * 4 + 2] += hk * w.z;
            acc[j4 * 4 + 3] += hk * w.w;
        }
    }
    float4* ob = (float4*)(g_rt + (size_t)node * HH);
#pragma unroll
    for (int j4 = 0; j4 < HH / 4; j4++)
        ob[j4] = make_float4(acc[j4 * 4], acc[j4 * 4 + 1], acc[j4 * 4 + 2], acc[j4 * 4 + 3]);
}

// ---------------- h2 = relu(agg + rt); pvsrc/pvrt scalar heads ----------------
__global__ void k_node2(const float* __restrict__ Wprel, const float* __restrict__ Wvrel,
                        const float* __restrict__ Wproot, const float* __restrict__ Wvroot,
                        const float* __restrict__ bp, const float* __restrict__ bv) {
    __shared__ float sWpr[HH], sWvr[HH], sWpo[HH], sWvo[HH];
    if (threadIdx.x < HH) {
        sWpr[threadIdx.x] = Wprel[threadIdx.x];
        sWvr[threadIdx.x] = Wvrel[threadIdx.x];
        sWpo[threadIdx.x] = Wproot[threadIdx.x];
        sWvo[threadIdx.x] = Wvroot[threadIdx.x];
    }
    __syncthreads();
    int node = blockIdx.x * blockDim.x + threadIdx.x;
    if (node >= NN) return;
    const float4* av = (const float4*)(g_agg + (size_t)node * HH);
    const float4* rv = (const float4*)(g_rt + (size_t)node * HH);
    float pr = 0.f, vr = 0.f, po = bp[0], vo = bv[0];
#pragma unroll
    for (int j4 = 0; j4 < HH / 4; j4++) {
        float4 a = av[j4];
        float4 r = rv[j4];
        float h0 = fmaxf(a.x + r.x, 0.f);
        float h1 = fmaxf(a.y + r.y, 0.f);
        float h2 = fmaxf(a.z + r.z, 0.f);
        float h3 = fmaxf(a.w + r.w, 0.f);
        int j = j4 * 4;
        pr += h0 * sWpr[j] + h1 * sWpr[j + 1] + h2 * sWpr[j + 2] + h3 * sWpr[j + 3];
        vr += h0 * sWvr[j] + h1 * sWvr[j + 1] + h2 * sWvr[j + 2] + h3 * sWvr[j + 3];
        po += h0 * sWpo[j] + h1 * sWpo[j + 1] + h2 * sWpo[j + 2] + h3 * sWpo[j + 3];
        vo += h0 * sWvo[j] + h1 * sWvo[j + 1] + h2 * sWvo[j + 2] + h3 * sWvo[j + 3];
    }
    *(float2*)(g_pvsrc + (size_t)node * 2) = make_float2(pr, vr);
    *(float2*)(g_pvrt + (size_t)node * 2) = make_float2(po, vo);
}

// ---------------- pv gather + finalize + softmax max (one warp per node) ----------------
__global__ void k_gpv_final(float* __restrict__ out) {
    __shared__ unsigned smax;
    if (threadIdx.x == 0) smax = 0u;
    __syncthreads();
    int gw = (blockIdx.x * blockDim.x + threadIdx.x) >> 5;
    int lane = threadIdx.x & 31;
    if (gw < NN) {
        int beg = g_off[gw];
        int cnt = g_cnt[gw];
        float ap = 0.f, av = 0.f;
        for (int idx = lane; idx < cnt; idx += 32) {
            int2 rec = g_edges[beg + idx];
            float w = __int_as_float(rec.y);
            float2 pv = *(const float2*)(g_pvsrc + (size_t)rec.x * 2);
            ap += w * pv.x;
            av += w * pv.y;
        }
#pragma unroll
        for (int o = 16; o; o >>= 1) {
            ap += __shfl_xor_sync(0xFFFFFFFFu, ap, o);
            av += __shfl_xor_sync(0xFFFFFFFFu, av, o);
        }
        if (lane == 0) {
            float2 rt = *(const float2*)(g_pvrt + (size_t)gw * 2);
            float p = ap + rt.x;
            float v = av + rt.y;
            float m = g_mask[gw];
            float pm = m * p;
            if (pm == 0.f) pm = __int_as_float(0xFF800000);
            g_pm[gw] = pm;
            out[NN + gw] = m * v;
            unsigned bb = __float_as_uint(pm);
            unsigned key = (bb & 0x80000000u) ? ~bb : (bb | 0x80000000u);
            if (key) atomicMax(&smax, key);
        }
    }
    __syncthreads();
    if (threadIdx.x == 0 && smax) atomicMax(&g_maxkey, smax);
}

// ---------------- softmax exp + sum ----------------
__global__ void k_final_b(float* __restrict__ out) {
    int node = blockIdx.x * blockDim.x + threadIdx.x;
    float e = 0.f;
    if (node < NN) {
        unsigned k = g_maxkey;
        float maxv = __uint_as_float((k & 0x80000000u) ? (k ^ 0x80000000u) : ~k);
        e = expf(g_pm[node] - maxv);
        out[node] = e;
    }
#pragma unroll
    for (int o = 16; o; o >>= 1) e += __shfl_xor_sync(0xFFFFFFFFu, e, o);
    if ((threadIdx.x & 31) == 0 && e != 0.f) atomicAdd(&g_sum, e);
}

// ---------------- softmax normalize ----------------
__global__ void k_final_c(float* __restrict__ out) {
    int node = blockIdx.x * blockDim.x + threadIdx.x;
    if (node < NN) out[node] = out[node] / g_sum;
}

// ---------------- launch ----------------
extern "C" void kernel_launch(void* const* d_in, const int* in_sizes, int n_in,
                              void* d_out, int out_size) {
    const float* x        = (const float*)d_in[0];
    const int*   ei       = (const int*)d_in[1];
    const float* ew       = (const float*)d_in[2];
    const int*   cur      = (const int*)d_in[3];
    const float* Win_rel  = (const float*)d_in[4];
    const float* bin_rel  = (const float*)d_in[5];
    const float* Win_root = (const float*)d_in[6];
    const float* Wh_rel   = (const float*)d_in[7];
    const float* bh_rel   = (const float*)d_in[8];
    const float* Wh_root  = (const float*)d_in[9];
    const float* Wp_rel   = (const float*)d_in[10];
    const float* bp_rel   = (const float*)d_in[11];
    const float* Wp_root  = (const float*)d_in[12];
    const float* Wv_rel   = (const float*)d_in[13];
    const float* bv_rel   = (const float*)d_in[14];
    const float* Wv_root  = (const float*)d_in[15];
    float* out = (float*)d_out;

    const int TB = 256;
    const int gn = (NN + TB - 1) / TB;
    const int ge = (EE + TB - 1) / TB;
    const int gwarp = (NN * 32 + TB - 1) / TB;

    k_xw64f<<<gn, TB>>>(x, Win_rel, Win_root, bin_rel);
    k_hist<<<ge, TB>>>(ei);
    k_scan1<<<NCH, 512>>>();
    k_scan2<<<1, 256>>>();
    k_scan3<<<NCH, 512>>>();
    k_scatter<<<ge, TB>>>(ei, ew);
    k_gather32<<<gwarp, TB>>>(cur, 1);
    k_node1<<<gn, TB>>>(Wh_rel, Wh_root, bh_rel);
    k_gather32<<<gwarp, TB>>>(cur, 0);
    k_node2<<<gn, TB>>>(Wp_rel, Wv_rel, Wp_root, Wv_root, bp_rel, bv_rel);
    k_gpv_final<<<gwarp, TB>>>(out);
    k_final_b<<<gn, TB>>>(out);
    k_final_c<<<gn, TB>>>(out);
}

// round 5
// speedup vs baseline: 1.0949x; 1.0949x over previous
#include <cuda_runtime.h>
#include <math.h>

#define NN 100000
#define EE 1600000
#define FIN 64
#define HH 32
#define NCH 196          // ceil(NN/512)

// ---------------- device scratch (static, allocation-free) ----------------
__device__ __align__(16) float g_xr[NN * HH];     // rel-transformed features for gather
__device__ __align__(16) float g_rt[NN * HH];     // root-transformed features (+bias)
__device__ __align__(16) float g_agg[NN * HH];    // gathered aggregation
__device__ __align__(16) float g_pvsrc[NN * 2];   // per-node (h2 . Wp_rel, h2 . Wv_rel)
__device__ __align__(16) float g_pvrt[NN * 2];    // per-node (h2 . Wp_root + bp, h2 . Wv_root + bv)
__device__ __align__(16) float g_pm[NN];
__device__ __align__(16) int2  g_edges[EE];       // dst-sorted (src, w-bits)
__device__ int g_cnt[NN];
__device__ int g_off[NN];
__device__ int g_wpos[NN];
__device__ int g_bsum[NCH];
__device__ int g_bbase[NCH];
__device__ int g_mlist[NN];
__device__ int g_mcnt;

// ---------------- f32x2 helpers ----------------
__device__ __forceinline__ void lds2u64(unsigned long long& a, unsigned long long& b, const float* p) {
    unsigned addr = (unsigned)__cvta_generic_to_shared(p);
    asm volatile("ld.shared.v2.u64 {%0,%1}, [%2];" : "=l"(a), "=l"(b) : "r"(addr));
}
__device__ __forceinline__ void fma2(unsigned long long& d, unsigned long long a, unsigned long long b) {
    asm volatile("fma.rn.f32x2 %0, %1, %2, %0;" : "+l"(d) : "l"(a), "l"(b));
}
__device__ __forceinline__ unsigned long long pack2(float x) {
    unsigned xi = __float_as_uint(x);
    unsigned long long r;
    asm volatile("mov.b64 %0, {%1,%1};" : "=l"(r) : "r"(xi));
    return r;
}

// ---------------- fused: xr = x@Win_rel, rt = x@Win_root + bin, zero scratch/out ----------------
__global__ __launch_bounds__(256) void k_xw64f(const float* __restrict__ x,
                                               const float* __restrict__ Wrel,
                                               const float* __restrict__ Wroot,
                                               const float* __restrict__ b,
                                               float* __restrict__ out) {
    __shared__ __align__(16) float sWa[FIN * HH];
    __shared__ __align__(16) float sWb[FIN * HH];
    __shared__ __align__(16) float sb[HH];
    for (int i = threadIdx.x; i < FIN * HH; i += blockDim.x) {
        sWa[i] = Wrel[i];
        sWb[i] = Wroot[i];
    }
    if (threadIdx.x < HH) sb[threadIdx.x] = b[threadIdx.x];
    __syncthreads();
    int node = blockIdx.x * blockDim.x + threadIdx.x;
    if (node == 0) g_mcnt = 0;
    if (node >= NN) return;
    g_cnt[node] = 0;
    out[node] = 0.f;          // softmax default (unmasked -> 0)
    out[NN + node] = 0.f;     // masked value default
    unsigned long long ar[HH / 2], br[HH / 2];
    const unsigned long long* sb64 = (const unsigned long long*)sb;
#pragma unroll
    for (int j = 0; j < HH / 2; j++) { ar[j] = 0ULL; br[j] = sb64[j]; }
    const float4* xv = (const float4*)(x + (size_t)node * FIN);
#pragma unroll
    for (int k4 = 0; k4 < FIN / 4; k4++) {
        float4 xk = xv[k4];
        float xs[4] = {xk.x, xk.y, xk.z, xk.w};
#pragma unroll
        for (int kk = 0; kk < 4; kk++) {
            int k = k4 * 4 + kk;
            unsigned long long xx = pack2(xs[kk]);
#pragma unroll
            for (int j = 0; j < 8; j++) {
                unsigned long long w0, w1;
                lds2u64(w0, w1, sWa + k * HH + j * 4);
                fma2(ar[j * 2], xx, w0);
                fma2(ar[j * 2 + 1], xx, w1);
            }
#pragma unroll
            for (int j = 0; j < 8; j++) {
                unsigned long long w0, w1;
                lds2u64(w0, w1, sWb + k * HH + j * 4);
                fma2(br[j * 2], xx, w0);
                fma2(br[j * 2 + 1], xx, w1);
            }
        }
    }
    ulonglong2* oa = (ulonglong2*)(g_xr + (size_t)node * HH);
    ulonglong2* ob = (ulonglong2*)(g_rt + (size_t)node * HH);
#pragma unroll
    for (int j = 0; j < 8; j++) {
        oa[j] = make_ulonglong2(ar[j * 2], ar[j * 2 + 1]);
        ob[j] = make_ulonglong2(br[j * 2], br[j * 2 + 1]);
    }
}

// ---------------- CSR build: histogram, 3-phase scan, scatter ----------------
__global__ void k_hist(const int* __restrict__ ei) {
    int e = blockIdx.x * blockDim.x + threadIdx.x;
    if (e >= EE) return;
    atomicAdd(&g_cnt[__ldg(ei + EE + e)], 1);
}

__global__ void k_scan1() {
    __shared__ int sh[512];
    int i = blockIdx.x * 512 + threadIdx.x;
    int v = (i < NN) ? g_cnt[i] : 0;
    sh[threadIdx.x] = v;
    __syncthreads();
#pragma unroll
    for (int s = 256; s; s >>= 1) {
        if (threadIdx.x < s) sh[threadIdx.x] += sh[threadIdx.x + s];
        __syncthreads();
    }
    if (threadIdx.x == 0) g_bsum[blockIdx.x] = sh[0];
}

__global__ void k_scan2() {
    __shared__ int sh[256];
    int tid = threadIdx.x;
    int v = (tid < NCH) ? g_bsum[tid] : 0;
    sh[tid] = v;
    __syncthreads();
    for (int off = 1; off < 256; off <<= 1) {
        int t = (tid >= off) ? sh[tid - off] : 0;
        __syncthreads();
        sh[tid] += t;
        __syncthreads();
    }
    if (tid < NCH) g_bbase[tid] = sh[tid] - v;
}

__global__ void k_scan3() {
    __shared__ int sh[512];
    int tid = threadIdx.x;
    int i = blockIdx.x * 512 + tid;
    int v = (i < NN) ? g_cnt[i] : 0;
    sh[tid] = v;
    __syncthreads();
    for (int off = 1; off < 512; off <<= 1) {
        int t = (tid >= off) ? sh[tid - off] : 0;
        __syncthreads();
        sh[tid] += t;
        __syncthreads();
    }
    if (i < NN) {
        int excl = sh[tid] - v + g_bbase[blockIdx.x];
        g_off[i] = excl;
        g_wpos[i] = excl;
    }
}

__global__ void k_scatter(const int* __restrict__ ei, const float* __restrict__ ew) {
    int e = blockIdx.x * blockDim.x + threadIdx.x;
    if (e >= EE) return;
    int s = __ldg(ei + e);
    int d = __ldg(ei + EE + e);
    float w = __ldg(ew + e);
    int pos = atomicAdd(&g_wpos[d], 1);
    g_edges[pos] = make_int2(s, __float_as_int(w));
}

// ---------------- gather: warp per dst node, lane = feature column, uniform edge loads ----------------
__global__ __launch_bounds__(256) void k_gather32(const int* __restrict__ curp, int do_mask) {
    int gw = (blockIdx.x * blockDim.x + threadIdx.x) >> 5;
    if (gw >= NN) return;
    int lane = threadIdx.x & 31;
    int beg = g_off[gw];
    int cnt = g_cnt[gw];
    int cur = do_mask ? __ldg(curp) : -1;
    const int2* ep = g_edges + beg;
    float a0 = 0.f, a1 = 0.f, a2 = 0.f, a3 = 0.f;
    int hit = 0;
    int t = 0;
    for (; t + 4 <= cnt; t += 4) {
        int2 e0 = ep[t], e1 = ep[t + 1], e2 = ep[t + 2], e3 = ep[t + 3];
        a0 = fmaf(__int_as_float(e0.y), g_xr[(size_t)e0.x * HH + lane], a0);
        a1 = fmaf(__int_as_float(e1.y), g_xr[(size_t)e1.x * HH + lane], a1);
        a2 = fmaf(__int_as_float(e2.y), g_xr[(size_t)e2.x * HH + lane], a2);
        a3 = fmaf(__int_as_float(e3.y), g_xr[(size_t)e3.x * HH + lane], a3);
        hit |= (e0.x == cur) | (e1.x == cur) | (e2.x == cur) | (e3.x == cur);
    }
    for (; t < cnt; t++) {
        int2 e = ep[t];
        a0 = fmaf(__int_as_float(e.y), g_xr[(size_t)e.x * HH + lane], a0);
        hit |= (e.x == cur);
    }
    g_agg[(size_t)gw * HH + lane] = (a0 + a1) + (a2 + a3);
    if (do_mask && lane == 0 && hit) {
        int p = atomicAdd(&g_mcnt, 1);
        g_mlist[p] = gw;
    }
}

// ---------------- h1 = relu(agg + rt); g_xr = h1@Wh_rel; g_rt = h1@Wh_root + bh ----------------
__global__ __launch_bounds__(256) void k_node1(const float* __restrict__ Whrel,
                                               const float* __restrict__ Whroot,
                                               const float* __restrict__ bh) {
    __shared__ __align__(16) float sWa[HH * HH];
    __shared__ __align__(16) float sWb[HH * HH];
    __shared__ __align__(16) float sb[HH];
    for (int i = threadIdx.x; i < HH * HH; i += blockDim.x) {
        sWa[i] = Whrel[i];
        sWb[i] = Whroot[i];
    }
    if (threadIdx.x < HH) sb[threadIdx.x] = bh[threadIdx.x];
    __syncthreads();
    int node = blockIdx.x * blockDim.x + threadIdx.x;
    if (node >= NN) return;
    float h1[HH];
    const float4* av = (const float4*)(g_agg + (size_t)node * HH);
    const float4* rv = (const float4*)(g_rt + (size_t)node * HH);
#pragma unroll
    for (int j4 = 0; j4 < HH / 4; j4++) {
        float4 a = av[j4];
        float4 r = rv[j4];
        h1[j4 * 4 + 0] = fmaxf(a.x + r.x, 0.f);
        h1[j4 * 4 + 1] = fmaxf(a.y + r.y, 0.f);
        h1[j4 * 4 + 2] = fmaxf(a.z + r.z, 0.f);
        h1[j4 * 4 + 3] = fmaxf(a.w + r.w, 0.f);
    }
    unsigned long long ar[HH / 2], br[HH / 2];
    const unsigned long long* sb64 = (const unsigned long long*)sb;
#pragma unroll
    for (int j = 0; j < HH / 2; j++) { ar[j] = 0ULL; br[j] = sb64[j]; }
#pragma unroll
    for (int k = 0; k < HH; k++) {
        unsigned long long xx = pack2(h1[k]);
#pragma unroll
        for (int j = 0; j < 8; j++) {
            unsigned long long w0, w1;
            lds2u64(w0, w1, sWa + k * HH + j * 4);
            fma2(ar[j * 2], xx, w0);
            fma2(ar[j * 2 + 1], xx, w1);
        }
#pragma unroll
        for (int j = 0; j < 8; j++) {
            unsigned long long w0, w1;
            lds2u64(w0, w1, sWb + k * HH + j * 4);
            fma2(br[j * 2], xx, w0);
            fma2(br[j * 2 + 1], xx, w1);
        }
    }
    ulonglong2* oa = (ulonglong2*)(g_xr + (size_t)node * HH);
    ulonglong2* ob = (ulonglong2*)(g_rt + (size_t)node * HH);
#pragma unroll
    for (int j = 0; j < 8; j++) {
        oa[j] = make_ulonglong2(ar[j * 2], ar[j * 2 + 1]);
        ob[j] = make_ulonglong2(br[j * 2], br[j * 2 + 1]);
    }
}

// ---------------- h2 = relu(agg + rt); pvsrc/pvrt scalar heads ----------------
__global__ void k_node2(const float* __restrict__ Wprel, const float* __restrict__ Wvrel,
                        const float* __restrict__ Wproot, const float* __restrict__ Wvroot,
                        const float* __restrict__ bp, const float* __restrict__ bv) {
    __shared__ float sWpr[HH], sWvr[HH], sWpo[HH], sWvo[HH];
    if (threadIdx.x < HH) {
        sWpr[threadIdx.x] = Wprel[threadIdx.x];
        sWvr[threadIdx.x] = Wvrel[threadIdx.x];
        sWpo[threadIdx.x] = Wproot[threadIdx.x];
        sWvo[threadIdx.x] = Wvroot[threadIdx.x];
    }
    __syncthreads();
    int node = blockIdx.x * blockDim.x + threadIdx.x;
    if (node >= NN) return;
    const float4* av = (const float4*)(g_agg + (size_t)node * HH);
    const float4* rv = (const float4*)(g_rt + (size_t)node * HH);
    float pr = 0.f, vr = 0.f, po = bp[0], vo = bv[0];
#pragma unroll
    for (int j4 = 0; j4 < HH / 4; j4++) {
        float4 a = av[j4];
        float4 r = rv[j4];
        float h0 = fmaxf(a.x + r.x, 0.f);
        float h1 = fmaxf(a.y + r.y, 0.f);
        float h2 = fmaxf(a.z + r.z, 0.f);
        float h3 = fmaxf(a.w + r.w, 0.f);
        int j = j4 * 4;
        pr += h0 * sWpr[j] + h1 * sWpr[j + 1] + h2 * sWpr[j + 2] + h3 * sWpr[j + 3];
        vr += h0 * sWvr[j] + h1 * sWvr[j + 1] + h2 * sWvr[j + 2] + h3 * sWvr[j + 3];
        po += h0 * sWpo[j] + h1 * sWpo[j + 1] + h2 * sWpo[j + 2] + h3 * sWpo[j + 3];
        vo += h0 * sWvo[j] + h1 * sWvo[j + 1] + h2 * sWvo[j + 2] + h3 * sWvo[j + 3];
    }
    *(float2*)(g_pvsrc + (size_t)node * 2) = make_float2(pr, vr);
    *(float2*)(g_pvrt + (size_t)node * 2) = make_float2(po, vo);
}

// ---------------- masked-node pv gather + softmax, single block ----------------
__global__ __launch_bounds__(1024) void k_gpv_final(float* __restrict__ out) {
    __shared__ float red[32];
    __shared__ float s_max, s_sum;
    int tid = threadIdx.x;
    int wid = tid >> 5, lane = tid & 31;
    int mcnt = g_mcnt;
    // phase 1: gather p,v for each masked node (one warp each)
    for (int m = wid; m < mcnt; m += 32) {
        int node = g_mlist[m];
        int beg = g_off[node];
        int cnt = g_cnt[node];
        float ap = 0.f, av = 0.f;
        for (int i = lane; i < cnt; i += 32) {
            int2 e = g_edges[beg + i];
            float w = __int_as_float(e.y);
            float2 pv = *(const float2*)(g_pvsrc + (size_t)e.x * 2);
            ap += w * pv.x;
            av += w * pv.y;
        }
#pragma unroll
        for (int o = 16; o; o >>= 1) {
            ap += __shfl_xor_sync(0xFFFFFFFFu, ap, o);
            av += __shfl_xor_sync(0xFFFFFFFFu, av, o);
        }
        if (lane == 0) {
            float2 rt = *(const float2*)(g_pvrt + (size_t)node * 2);
            float p = ap + rt.x;
            float v = av + rt.y;
            float pm = (p == 0.f) ? __int_as_float(0xFF800000) : p;  // mask=1 here; p==0 -> -inf per reference
            g_pm[node] = pm;
            out[NN + node] = v;
        }
    }
    __syncthreads();
    // phase 2: block max over masked pm
    float mx = __int_as_float(0xFF800000);
    for (int m = tid; m < mcnt; m += 1024) mx = fmaxf(mx, g_pm[g_mlist[m]]);
#pragma unroll
    for (int o = 16; o; o >>= 1) mx = fmaxf(mx, __shfl_xor_sync(0xFFFFFFFFu, mx, o));
    if (lane == 0) red[wid] = mx;
    __syncthreads();
    if (tid < 32) {
        float v = red[tid];
#pragma unroll
        for (int o = 16; o; o >>= 1) v = fmaxf(v, __shfl_xor_sync(0xFFFFFFFFu, v, o));
        if (tid == 0) s_max = v;
    }
    __syncthreads();
    float maxv = s_max;
    // phase 3: sum of exp
    float sm = 0.f;
    for (int m = tid; m < mcnt; m += 1024) {
        int node = g_mlist[m];
        float e = expf(g_pm[node] - maxv);
        g_pm[node] = e;
        sm += e;
    }
#pragma unroll
    for (int o = 16; o; o >>= 1) sm += __shfl_xor_sync(0xFFFFFFFFu, sm, o);
    if (lane == 0) red[wid] = sm;
    __syncthreads();
    if (tid < 32) {
        float v = red[tid];
#pragma unroll
        for (int o = 16; o; o >>= 1) v += __shfl_xor_sync(0xFFFFFFFFu, v, o);
        if (tid == 0) s_sum = v;
    }
    __syncthreads();
    float inv = 1.f / s_sum;
    // phase 4: write normalized softmax for masked nodes (rest already 0)
    for (int m = tid; m < mcnt; m += 1024) {
        int node = g_mlist[m];
        out[node] = g_pm[node] * inv;
    }
}

// ---------------- launch ----------------
extern "C" void kernel_launch(void* const* d_in, const int* in_sizes, int n_in,
                              void* d_out, int out_size) {
    const float* x        = (const float*)d_in[0];
    const int*   ei       = (const int*)d_in[1];
    const float* ew       = (const float*)d_in[2];
    const int*   cur      = (const int*)d_in[3];
    const float* Win_rel  = (const float*)d_in[4];
    const float* bin_rel  = (const float*)d_in[5];
    const float* Win_root = (const float*)d_in[6];
    const float* Wh_rel   = (const float*)d_in[7];
    const float* bh_rel   = (const float*)d_in[8];
    const float* Wh_root  = (const float*)d_in[9];
    const float* Wp_rel   = (const float*)d_in[10];
    const float* bp_rel   = (const float*)d_in[11];
    const float* Wp_root  = (const float*)d_in[12];
    const float* Wv_rel   = (const float*)d_in[13];
    const float* bv_rel   = (const float*)d_in[14];
    const float* Wv_root  = (const float*)d_in[15];
    float* out = (float*)d_out;

    const int TB = 256;
    const int gn = (NN + TB - 1) / TB;
    const int ge = (EE + TB - 1) / TB;
    const int gwarp = (NN * 32 + TB - 1) / TB;

    k_xw64f<<<gn, TB>>>(x, Win_rel, Win_root, bin_rel, out);
    k_hist<<<ge, TB>>>(ei);
    k_scan1<<<NCH, 512>>>();
    k_scan2<<<1, 256>>>();
    k_scan3<<<NCH, 512>>>();
    k_scatter<<<ge, TB>>>(ei, ew);
    k_gather32<<<gwarp, TB>>>(cur, 1);
    k_node1<<<gn, TB>>>(Wh_rel, Wh_root, bh_rel);
    k_gather32<<<gwarp, TB>>>(cur, 0);
    k_node2<<<gn, TB>>>(Wp_rel, Wv_rel, Wp_root, Wv_root, bp_rel, bv_rel);
    k_gpv_final<<<1, 1024>>>(out);
}

// round 6
// speedup vs baseline: 1.4298x; 1.3059x over previous
#include <cuda_runtime.h>
#include <math.h>

#define NN 100000
#define EE 1600000
#define FIN 64
#define HH 32
#define NCH 196          // ceil(NN/512)

// ---------------- device scratch (static, allocation-free) ----------------
__device__ __align__(16) float g_xr[NN * HH];     // rel-transformed features for gather
__device__ __align__(16) float g_rt[NN * HH];     // root-transformed features (+bias)
__device__ __align__(16) float g_h1[NN * HH];     // relu(agg + rt) after gather1
__device__ __align__(16) float g_pvsrc[NN * 2];   // per-node (h2 . Wp_rel, h2 . Wv_rel)
__device__ __align__(16) float g_pvrt[NN * 2];    // per-node (h2 . Wp_root + bp, h2 . Wv_root + bv)
__device__ __align__(16) float g_pm[NN];
__device__ __align__(16) int2  g_edges[EE];       // dst-sorted (src, w-bits)
__device__ int g_cnt[NN];
__device__ int g_off[NN];
__device__ int g_wpos[NN];
__device__ int g_bsum[NCH];
__device__ int g_mlist[NN];
__device__ int g_mcnt;
__device__ int g_done1;
__device__ int g_done2;

// ---------------- f32x2 helpers ----------------
__device__ __forceinline__ void lds2u64(unsigned long long& a, unsigned long long& b, const float* p) {
    unsigned addr = (unsigned)__cvta_generic_to_shared(p);
    asm volatile("ld.shared.v2.u64 {%0,%1}, [%2];" : "=l"(a), "=l"(b) : "r"(addr));
}
__device__ __forceinline__ void fma2(unsigned long long& d, unsigned long long a, unsigned long long b) {
    asm volatile("fma.rn.f32x2 %0, %1, %2, %0;" : "+l"(d) : "l"(a), "l"(b));
}
__device__ __forceinline__ unsigned long long pack2(float x) {
    unsigned xi = __float_as_uint(x);
    unsigned long long r;
    asm volatile("mov.b64 %0, {%1,%1};" : "=l"(r) : "r"(xi));
    return r;
}

// ---------------- fused: xr = x@Win_rel, rt = x@Win_root + bin, zero scratch/out ----------------
__global__ __launch_bounds__(256) void k_xw64f(const float* __restrict__ x,
                                               const float* __restrict__ Wrel,
                                               const float* __restrict__ Wroot,
                                               const float* __restrict__ b,
                                               float* __restrict__ out) {
    __shared__ __align__(16) float sWa[FIN * HH];
    __shared__ __align__(16) float sWb[FIN * HH];
    __shared__ __align__(16) float sb[HH];
    for (int i = threadIdx.x; i < FIN * HH; i += blockDim.x) {
        sWa[i] = Wrel[i];
        sWb[i] = Wroot[i];
    }
    if (threadIdx.x < HH) sb[threadIdx.x] = b[threadIdx.x];
    __syncthreads();
    int node = blockIdx.x * blockDim.x + threadIdx.x;
    if (node == 0) { g_mcnt = 0; g_done1 = 0; g_done2 = 0; }
    if (node >= NN) return;
    g_cnt[node] = 0;
    out[node] = 0.f;          // softmax default (unmasked -> 0)
    out[NN + node] = 0.f;     // masked value default
    unsigned long long ar[HH / 2], br[HH / 2];
    const unsigned long long* sb64 = (const unsigned long long*)sb;
#pragma unroll
    for (int j = 0; j < HH / 2; j++) { ar[j] = 0ULL; br[j] = sb64[j]; }
    const float4* xv = (const float4*)(x + (size_t)node * FIN);
#pragma unroll
    for (int k4 = 0; k4 < FIN / 4; k4++) {
        float4 xk = xv[k4];
        float xs[4] = {xk.x, xk.y, xk.z, xk.w};
#pragma unroll
        for (int kk = 0; kk < 4; kk++) {
            int k = k4 * 4 + kk;
            unsigned long long xx = pack2(xs[kk]);
#pragma unroll
            for (int j = 0; j < 8; j++) {
                unsigned long long w0, w1;
                lds2u64(w0, w1, sWa + k * HH + j * 4);
                fma2(ar[j * 2], xx, w0);
                fma2(ar[j * 2 + 1], xx, w1);
            }
#pragma unroll
            for (int j = 0; j < 8; j++) {
                unsigned long long w0, w1;
                lds2u64(w0, w1, sWb + k * HH + j * 4);
                fma2(br[j * 2], xx, w0);
                fma2(br[j * 2 + 1], xx, w1);
            }
        }
    }
    ulonglong2* oa = (ulonglong2*)(g_xr + (size_t)node * HH);
    ulonglong2* ob = (ulonglong2*)(g_rt + (size_t)node * HH);
#pragma unroll
    for (int j = 0; j < 8; j++) {
        oa[j] = make_ulonglong2(ar[j * 2], ar[j * 2 + 1]);
        ob[j] = make_ulonglong2(br[j * 2], br[j * 2 + 1]);
    }
}

// ---------------- histogram of destinations ----------------
__global__ void k_hist(const int* __restrict__ ei) {
    int e = blockIdx.x * blockDim.x + threadIdx.x;
    if (e >= EE) return;
    atomicAdd(&g_cnt[__ldg(ei + EE + e)], 1);
}

// ---------------- fused scan + scatter: 196 all-resident blocks, flag-based grid syncs ----------------
__global__ __launch_bounds__(512) void k_scan_scatter(const int* __restrict__ ei,
                                                      const float* __restrict__ ew) {
    __shared__ int sh[512];
    __shared__ int sred[512];
    int tid = threadIdx.x;
    int bid = blockIdx.x;
    int i = bid * 512 + tid;
    int v = (i < NN) ? g_cnt[i] : 0;
    sh[tid] = v;
    __syncthreads();
    // Hillis-Steele inclusive scan
    for (int off = 1; off < 512; off <<= 1) {
        int t = (tid >= off) ? sh[tid - off] : 0;
        __syncthreads();
        sh[tid] += t;
        __syncthreads();
    }
    if (tid == 511) g_bsum[bid] = sh[511];
    // grid sync 1: all block sums published
    __threadfence();
    __syncthreads();
    if (tid == 0) {
        atomicAdd(&g_done1, 1);
        while (atomicAdd(&g_done1, 0) < NCH) { }
    }
    __syncthreads();
    __threadfence();
    // each block computes its own base = sum of g_bsum[0..bid-1]
    sred[tid] = (tid < bid) ? g_bsum[tid] : 0;
    __syncthreads();
#pragma unroll
    for (int s = 256; s; s >>= 1) {
        if (tid < s) sred[tid] += sred[tid + s];
        __syncthreads();
    }
    int base = sred[0];
    if (i < NN) {
        int excl = base + sh[tid] - v;
        g_off[i] = excl;
        g_wpos[i] = excl;
    }
    // grid sync 2: all offsets written
    __threadfence();
    __syncthreads();
    if (tid == 0) {
        atomicAdd(&g_done2, 1);
        while (atomicAdd(&g_done2, 0) < NCH) { }
    }
    __syncthreads();
    __threadfence();
    // scatter, grid-stride over edges
    int gtid = bid * 512 + tid;
    for (int e = gtid; e < EE; e += NCH * 512) {
        int s = __ldg(ei + e);
        int d = __ldg(ei + EE + e);
        float w = __ldg(ew + e);
        int pos = atomicAdd(&g_wpos[d], 1);
        g_edges[pos] = make_int2(s, __float_as_int(w));
    }
}

// ---------------- gather1: 8 lanes/node, float4/lane; h1 = relu(agg + rt); mask list ----------------
__global__ __launch_bounds__(256) void k_gather1(const int* __restrict__ curp) {
    int gt = blockIdx.x * blockDim.x + threadIdx.x;
    int node = gt >> 3;
    if (node >= NN) return;
    int sub = gt & 7;
    int beg = g_off[node];
    int cnt = g_cnt[node];
    int cur = __ldg(curp);
    const int2* ep = g_edges + beg;
    float4 a0 = make_float4(0.f, 0.f, 0.f, 0.f);
    float4 a1 = make_float4(0.f, 0.f, 0.f, 0.f);
    int hit = 0;
    int t = 0;
    for (; t + 2 <= cnt; t += 2) {
        int2 e0 = ep[t], e1 = ep[t + 1];
        float w0 = __int_as_float(e0.y), w1 = __int_as_float(e1.y);
        float4 r0 = ((const float4*)(g_xr + (size_t)e0.x * HH))[sub];
        float4 r1 = ((const float4*)(g_xr + (size_t)e1.x * HH))[sub];
        a0.x = fmaf(w0, r0.x, a0.x); a0.y = fmaf(w0, r0.y, a0.y);
        a0.z = fmaf(w0, r0.z, a0.z); a0.w = fmaf(w0, r0.w, a0.w);
        a1.x = fmaf(w1, r1.x, a1.x); a1.y = fmaf(w1, r1.y, a1.y);
        a1.z = fmaf(w1, r1.z, a1.z); a1.w = fmaf(w1, r1.w, a1.w);
        hit |= (e0.x == cur) | (e1.x == cur);
    }
    if (t < cnt) {
        int2 e0 = ep[t];
        float w0 = __int_as_float(e0.y);
        float4 r0 = ((const float4*)(g_xr + (size_t)e0.x * HH))[sub];
        a0.x = fmaf(w0, r0.x, a0.x); a0.y = fmaf(w0, r0.y, a0.y);
        a0.z = fmaf(w0, r0.z, a0.z); a0.w = fmaf(w0, r0.w, a0.w);
        hit |= (e0.x == cur);
    }
    float4 rt = ((const float4*)(g_rt + (size_t)node * HH))[sub];
    float4 h;
    h.x = fmaxf(a0.x + a1.x + rt.x, 0.f);
    h.y = fmaxf(a0.y + a1.y + rt.y, 0.f);
    h.z = fmaxf(a0.z + a1.z + rt.z, 0.f);
    h.w = fmaxf(a0.w + a1.w + rt.w, 0.f);
    ((float4*)(g_h1 + (size_t)node * HH))[sub] = h;
    if (sub == 0 && hit) {
        int p = atomicAdd(&g_mcnt, 1);
        g_mlist[p] = node;
    }
}

// ---------------- node1: xr = h1@Wh_rel; rt = h1@Wh_root + bh ----------------
__global__ __launch_bounds__(256) void k_node1(const float* __restrict__ Whrel,
                                               const float* __restrict__ Whroot,
                                               const float* __restrict__ bh) {
    __shared__ __align__(16) float sWa[HH * HH];
    __shared__ __align__(16) float sWb[HH * HH];
    __shared__ __align__(16) float sb[HH];
    for (int i = threadIdx.x; i < HH * HH; i += blockDim.x) {
        sWa[i] = Whrel[i];
        sWb[i] = Whroot[i];
    }
    if (threadIdx.x < HH) sb[threadIdx.x] = bh[threadIdx.x];
    __syncthreads();
    int node = blockIdx.x * blockDim.x + threadIdx.x;
    if (node >= NN) return;
    float h1[HH];
    const float4* hv = (const float4*)(g_h1 + (size_t)node * HH);
#pragma unroll
    for (int j4 = 0; j4 < HH / 4; j4++) {
        float4 a = hv[j4];
        h1[j4 * 4 + 0] = a.x;
        h1[j4 * 4 + 1] = a.y;
        h1[j4 * 4 + 2] = a.z;
        h1[j4 * 4 + 3] = a.w;
    }
    unsigned long long ar[HH / 2], br[HH / 2];
    const unsigned long long* sb64 = (const unsigned long long*)sb;
#pragma unroll
    for (int j = 0; j < HH / 2; j++) { ar[j] = 0ULL; br[j] = sb64[j]; }
#pragma unroll
    for (int k = 0; k < HH; k++) {
        unsigned long long xx = pack2(h1[k]);
#pragma unroll
        for (int j = 0; j < 8; j++) {
            unsigned long long w0, w1;
            lds2u64(w0, w1, sWa + k * HH + j * 4);
            fma2(ar[j * 2], xx, w0);
            fma2(ar[j * 2 + 1], xx, w1);
        }
#pragma unroll
        for (int j = 0; j < 8; j++) {
            unsigned long long w0, w1;
            lds2u64(w0, w1, sWb + k * HH + j * 4);
            fma2(br[j * 2], xx, w0);
            fma2(br[j * 2 + 1], xx, w1);
        }
    }
    ulonglong2* oa = (ulonglong2*)(g_xr + (size_t)node * HH);
    ulonglong2* ob = (ulonglong2*)(g_rt + (size_t)node * HH);
#pragma unroll
    for (int j = 0; j < 8; j++) {
        oa[j] = make_ulonglong2(ar[j * 2], ar[j * 2 + 1]);
        ob[j] = make_ulonglong2(br[j * 2], br[j * 2 + 1]);
    }
}

// ---------------- gather2: agg + relu + 4 scalar heads fused (8 lanes/node) ----------------
__global__ __launch_bounds__(256) void k_gather2(const float* __restrict__ Wprel,
                                                 const float* __restrict__ Wvrel,
                                                 const float* __restrict__ Wproot,
                                                 const float* __restrict__ Wvroot,
                                                 const float* __restrict__ bp,
                                                 const float* __restrict__ bv) {
    int gt = blockIdx.x * blockDim.x + threadIdx.x;
    int node = gt >> 3;
    if (node >= NN) return;
    int sub = gt & 7;
    int beg = g_off[node];
    int cnt = g_cnt[node];
    const int2* ep = g_edges + beg;
    float4 a0 = make_float4(0.f, 0.f, 0.f, 0.f);
    float4 a1 = make_float4(0.f, 0.f, 0.f, 0.f);
    int t = 0;
    for (; t + 2 <= cnt; t += 2) {
        int2 e0 = ep[t], e1 = ep[t + 1];
        float w0 = __int_as_float(e0.y), w1 = __int_as_float(e1.y);
        float4 r0 = ((const float4*)(g_xr + (size_t)e0.x * HH))[sub];
        float4 r1 = ((const float4*)(g_xr + (size_t)e1.x * HH))[sub];
        a0.x = fmaf(w0, r0.x, a0.x); a0.y = fmaf(w0, r0.y, a0.y);
        a0.z = fmaf(w0, r0.z, a0.z); a0.w = fmaf(w0, r0.w, a0.w);
        a1.x = fmaf(w1, r1.x, a1.x); a1.y = fmaf(w1, r1.y, a1.y);
        a1.z = fmaf(w1, r1.z, a1.z); a1.w = fmaf(w1, r1.w, a1.w);
    }
    if (t < cnt) {
        int2 e0 = ep[t];
        float w0 = __int_as_float(e0.y);
        float4 r0 = ((const float4*)(g_xr + (size_t)e0.x * HH))[sub];
        a0.x = fmaf(w0, r0.x, a0.x); a0.y = fmaf(w0, r0.y, a0.y);
        a0.z = fmaf(w0, r0.z, a0.z); a0.w = fmaf(w0, r0.w, a0.w);
    }
    float4 rt = ((const float4*)(g_rt + (size_t)node * HH))[sub];
    float h0 = fmaxf(a0.x + a1.x + rt.x, 0.f);
    float h1 = fmaxf(a0.y + a1.y + rt.y, 0.f);
    float h2 = fmaxf(a0.z + a1.z + rt.z, 0.f);
    float h3 = fmaxf(a0.w + a1.w + rt.w, 0.f);
    float4 wpr = __ldg((const float4*)Wprel + sub);
    float4 wvr = __ldg((const float4*)Wvrel + sub);
    float4 wpo = __ldg((const float4*)Wproot + sub);
    float4 wvo = __ldg((const float4*)Wvroot + sub);
    float pr = h0 * wpr.x + h1 * wpr.y + h2 * wpr.z + h3 * wpr.w;
    float vr = h0 * wvr.x + h1 * wvr.y + h2 * wvr.z + h3 * wvr.w;
    float po = h0 * wpo.x + h1 * wpo.y + h2 * wpo.z + h3 * wpo.w;
    float vo = h0 * wvo.x + h1 * wvo.y + h2 * wvo.z + h3 * wvo.w;
#pragma unroll
    for (int o = 4; o; o >>= 1) {
        pr += __shfl_xor_sync(0xFFFFFFFFu, pr, o);
        vr += __shfl_xor_sync(0xFFFFFFFFu, vr, o);
        po += __shfl_xor_sync(0xFFFFFFFFu, po, o);
        vo += __shfl_xor_sync(0xFFFFFFFFu, vo, o);
    }
    if (sub == 0) {
        *(float2*)(g_pvsrc + (size_t)node * 2) = make_float2(pr, vr);
        *(float2*)(g_pvrt + (size_t)node * 2) = make_float2(po + __ldg(bp), vo + __ldg(bv));
    }
}

// ---------------- masked-node pv gather + softmax, single block ----------------
__global__ __launch_bounds__(1024) void k_gpv_final(float* __restrict__ out) {
    __shared__ float red[32];
    __shared__ float s_max, s_sum;
    int tid = threadIdx.x;
    int wid = tid >> 5, lane = tid & 31;
    int mcnt = g_mcnt;
    for (int m = wid; m < mcnt; m += 32) {
        int node = g_mlist[m];
        int beg = g_off[node];
        int cnt = g_cnt[node];
        float ap = 0.f, av = 0.f;
        for (int i = lane; i < cnt; i += 32) {
            int2 e = g_edges[beg + i];
            float w = __int_as_float(e.y);
            float2 pv = *(const float2*)(g_pvsrc + (size_t)e.x * 2);
            ap += w * pv.x;
            av += w * pv.y;
        }
#pragma unroll
        for (int o = 16; o; o >>= 1) {
            ap += __shfl_xor_sync(0xFFFFFFFFu, ap, o);
            av += __shfl_xor_sync(0xFFFFFFFFu, av, o);
        }
        if (lane == 0) {
            float2 rt = *(const float2*)(g_pvrt + (size_t)node * 2);
            float p = ap + rt.x;
            float v = av + rt.y;
            float pm = (p == 0.f) ? __int_as_float(0xFF800000) : p;
            g_pm[node] = pm;
            out[NN + node] = v;
        }
    }
    __syncthreads();
    float mx = __int_as_float(0xFF800000);
    for (int m = tid; m < mcnt; m += 1024) mx = fmaxf(mx, g_pm[g_mlist[m]]);
#pragma unroll
    for (int o = 16; o; o >>= 1) mx = fmaxf(mx, __shfl_xor_sync(0xFFFFFFFFu, mx, o));
    if (lane == 0) red[wid] = mx;
    __syncthreads();
    if (tid < 32) {
        float v = red[tid];
#pragma unroll
        for (int o = 16; o; o >>= 1) v = fmaxf(v, __shfl_xor_sync(0xFFFFFFFFu, v, o));
        if (tid == 0) s_max = v;
    }
    __syncthreads();
    float maxv = s_max;
    float sm = 0.f;
    for (int m = tid; m < mcnt; m += 1024) {
        int node = g_mlist[m];
        float e = expf(g_pm[node] - maxv);
        g_pm[node] = e;
        sm += e;
    }
#pragma unroll
    for (int o = 16; o; o >>= 1) sm += __shfl_xor_sync(0xFFFFFFFFu, sm, o);
    if (lane == 0) red[wid] = sm;
    __syncthreads();
    if (tid < 32) {
        float v = red[tid];
#pragma unroll
        for (int o = 16; o; o >>= 1) v += __shfl_xor_sync(0xFFFFFFFFu, v, o);
        if (tid == 0) s_sum = v;
    }
    __syncthreads();
    float inv = 1.f / s_sum;
    for (int m = tid; m < mcnt; m += 1024) {
        int node = g_mlist[m];
        out[node] = g_pm[node] * inv;
    }
}

// ---------------- launch ----------------
extern "C" void kernel_launch(void* const* d_in, const int* in_sizes, int n_in,
                              void* d_out, int out_size) {
    const float* x        = (const float*)d_in[0];
    const int*   ei       = (const int*)d_in[1];
    const float* ew       = (const float*)d_in[2];
    const int*   cur      = (const int*)d_in[3];
    const float* Win_rel  = (const float*)d_in[4];
    const float* bin_rel  = (const float*)d_in[5];
    const float* Win_root = (const float*)d_in[6];
    const float* Wh_rel   = (const float*)d_in[7];
    const float* bh_rel   = (const float*)d_in[8];
    const float* Wh_root  = (const float*)d_in[9];
    const float* Wp_rel   = (const float*)d_in[10];
    const float* bp_rel   = (const float*)d_in[11];
    const float* Wp_root  = (const float*)d_in[12];
    const float* Wv_rel   = (const float*)d_in[13];
    const float* bv_rel   = (const float*)d_in[14];
    const float* Wv_root  = (const float*)d_in[15];
    float* out = (float*)d_out;

    const int TB = 256;
    const int gn = (NN + TB - 1) / TB;
    const int ge = (EE + TB - 1) / TB;
    const int gg = (NN * 8 + TB - 1) / TB;   // 8 lanes per node

    k_xw64f<<<gn, TB>>>(x, Win_rel, Win_root, bin_rel, out);        // 0
    k_hist<<<ge, TB>>>(ei);                                          // 1
    k_scan_scatter<<<NCH, 512>>>(ei, ew);                            // 2
    k_gather1<<<gg, TB>>>(cur);                                      // 3
    k_node1<<<gn, TB>>>(Wh_rel, Wh_root, bh_rel);                    // 4
    k_gather2<<<gg, TB>>>(Wp_rel, Wv_rel, Wp_root, Wv_root, bp_rel, bv_rel);  // 5 <- ncu capture
    k_gpv_final<<<1, 1024>>>(out);                                   // 6
}